// round 15
// baseline (speedup 1.0000x reference)
#include <cuda_runtime.h>
#include <cuda_fp16.h>
#include <math.h>
#include <stdint.h>

// Problem constants
constexpr int cB  = 8;
constexpr int cSQ = 512;
constexpr int cSK = 1024;
constexpr int cD  = 1024;
constexpr int cH  = 16;
constexpr int cDK = 64;
constexpr int cF  = 4096;

// ---------------------------------------------------------------------------
// Scratch (device globals; no allocations allowed)
// ---------------------------------------------------------------------------
__device__ float g_bufQ [(size_t)cB*cSQ*cD];
__device__ float g_bufK [(size_t)cB*cSQ*cD];    // self K
__device__ float g_bufV [(size_t)cB*cSQ*cD];    // self V
__device__ float g_bufK2[(size_t)cB*cSK*cD];    // cross K
__device__ float g_bufV2[(size_t)cB*cSK*cD];    // cross V
__device__ float g_bufC [(size_t)cB*cSQ*cD];
__device__ float g_bufO [(size_t)cB*cSQ*cD];
__device__ float g_bufX1[(size_t)cB*cSQ*cD];
__device__ float g_bufX2[(size_t)cB*cSQ*cD];
__device__ float g_bufF [(size_t)cB*cSQ*cF];

// ---------------------------------------------------------------------------
// helpers
// ---------------------------------------------------------------------------
__device__ __forceinline__ void mma_f16(float c[4],
    uint32_t a0, uint32_t a1, uint32_t a2, uint32_t a3,
    uint32_t b0, uint32_t b1)
{
    asm volatile(
        "mma.sync.aligned.m16n8k16.row.col.f32.f16.f16.f32 "
        "{%0,%1,%2,%3}, {%4,%5,%6,%7}, {%8,%9}, {%0,%1,%2,%3};"
        : "+f"(c[0]), "+f"(c[1]), "+f"(c[2]), "+f"(c[3])
        : "r"(a0), "r"(a1), "r"(a2), "r"(a3), "r"(b0), "r"(b1));
}

__device__ __forceinline__ uint32_t h2u(__half2 h) {
    return *reinterpret_cast<uint32_t*>(&h);
}

__device__ __forceinline__ uint4 pack8(float4 a, float4 b) {
    return make_uint4(
        h2u(__floats2half2_rn(a.x, a.y)), h2u(__floats2half2_rn(a.z, a.w)),
        h2u(__floats2half2_rn(b.x, b.y)), h2u(__floats2half2_rn(b.z, b.w)));
}

// Pointer set for multi-output GEMM (blockIdx.z selects)
struct GemmSet {
    const float* W[3];
    const float* bias[3];
    float*       C[3];
};

// ---------------------------------------------------------------------------
// fp16 GEMM (proven body): C[M,N] = A[M,K] @ W[K,N] + bias (+ReLU).
// ---------------------------------------------------------------------------
template<bool RELU>
__global__ __launch_bounds__(256, 2) void gemm_fp16(
    const float* __restrict__ A, GemmSet set,
    int M, int N, int K)
{
    const float* __restrict__ W    = set.W[blockIdx.z];
    const float* __restrict__ bias = set.bias[blockIdx.z];
    float* __restrict__       C    = set.C[blockIdx.z];

    __shared__ __half2 As2[128 * 12];
    __shared__ __half2 Bs2[8 * 136];

    const int tid  = threadIdx.x;
    const int bx   = blockIdx.x, by = blockIdx.y;
    const int warp = tid >> 5, lane = tid & 31;
    const int g = lane >> 2, tig = lane & 3;
    const int wm = warp >> 2;
    const int wn = warp & 3;

    const int ar  = tid >> 1;
    const int ac2 = (tid & 1) * 4;
    const float* Asrc = A + (size_t)(by*128 + ar)*K + ac2*2;

    const int bk2 = warp;
    const int bn  = lane * 4;
    const float* Bsrc0 = W + (size_t)(2*bk2    )*N + bx*128 + bn;
    const float* Bsrc1 = W + (size_t)(2*bk2 + 1)*N + bx*128 + bn;

    const int nk = K >> 4;
    float acc[4][4][4] = {};

    float4 pa0 = *(const float4*)(Asrc);
    float4 pa1 = *(const float4*)(Asrc + 4);
    float4 pb0 = *(const float4*)(Bsrc0);
    float4 pb1 = *(const float4*)(Bsrc1);

    for (int kt = 0; kt < nk; kt++) {
        {
            *(uint4*)&As2[ar*12 + ac2] = pack8(pa0, pa1);
            __half2 b0 = __floats2half2_rn(pb0.x, pb1.x);
            __half2 b1 = __floats2half2_rn(pb0.y, pb1.y);
            __half2 b2 = __floats2half2_rn(pb0.z, pb1.z);
            __half2 b3 = __floats2half2_rn(pb0.w, pb1.w);
            *(uint4*)&Bs2[bk2*136 + bn] = make_uint4(h2u(b0), h2u(b1), h2u(b2), h2u(b3));
        }
        __syncthreads();

        if (kt + 1 < nk) {
            const int kn = (kt + 1) << 4;
            pa0 = *(const float4*)(Asrc + kn);
            pa1 = *(const float4*)(Asrc + kn + 4);
            pb0 = *(const float4*)(Bsrc0 + (size_t)kn*N);
            pb1 = *(const float4*)(Bsrc1 + (size_t)kn*N);
        }

        uint32_t af[4][4];
#pragma unroll
        for (int mt = 0; mt < 4; mt++) {
            int r0 = wm*64 + mt*16 + g;
            af[mt][0] = *(uint32_t*)&As2[r0*12 + tig];
            af[mt][1] = *(uint32_t*)&As2[(r0 + 8)*12 + tig];
            af[mt][2] = *(uint32_t*)&As2[r0*12 + 4 + tig];
            af[mt][3] = *(uint32_t*)&As2[(r0 + 8)*12 + 4 + tig];
        }
        uint32_t bf[4][2];
#pragma unroll
        for (int nt = 0; nt < 4; nt++) {
            int n = wn*32 + nt*8 + g;
            bf[nt][0] = *(uint32_t*)&Bs2[tig*136 + n];
            bf[nt][1] = *(uint32_t*)&Bs2[(4 + tig)*136 + n];
        }
#pragma unroll
        for (int mt = 0; mt < 4; mt++)
#pragma unroll
            for (int nt = 0; nt < 4; nt++)
                mma_f16(acc[mt][nt], af[mt][0], af[mt][1], af[mt][2], af[mt][3],
                        bf[nt][0], bf[nt][1]);
        __syncthreads();
    }

#pragma unroll
    for (int mt = 0; mt < 4; mt++) {
#pragma unroll
        for (int nt = 0; nt < 4; nt++) {
            int row0 = by*128 + wm*64 + mt*16 + g;
            int col  = bx*128 + wn*32 + nt*8 + 2*tig;
            float b0 = bias[col], b1 = bias[col + 1];
            float2 v0 = { acc[mt][nt][0] + b0, acc[mt][nt][1] + b1 };
            float2 v1 = { acc[mt][nt][2] + b0, acc[mt][nt][3] + b1 };
            if (RELU) {
                v0.x = fmaxf(v0.x, 0.f); v0.y = fmaxf(v0.y, 0.f);
                v1.x = fmaxf(v1.x, 0.f); v1.y = fmaxf(v1.y, 0.f);
            }
            *(float2*)&C[(size_t)row0*N + col]       = v0;
            *(float2*)&C[(size_t)(row0 + 8)*N + col] = v1;
        }
    }
}

static inline GemmSet mkset(const float* w0, const float* b0, float* c0,
                            const float* w1 = nullptr, const float* b1 = nullptr, float* c1 = nullptr,
                            const float* w2 = nullptr, const float* b2 = nullptr, float* c2 = nullptr)
{
    GemmSet s;
    s.W[0] = w0; s.bias[0] = b0; s.C[0] = c0;
    s.W[1] = w1; s.bias[1] = b1; s.C[1] = c1;
    s.W[2] = w2; s.bias[2] = b2; s.C[2] = c2;
    return s;
}

// ---------------------------------------------------------------------------
// Fused SELF attention (causal): 64 q-rows/block, K/V register prefetch.
// Softmax stores raw exp; AV epilogue scales by rowInv (fp32).
// ---------------------------------------------------------------------------
__global__ __launch_bounds__(256) void attn_self_fused(
    const float* __restrict__ Q, const float* __restrict__ K,
    const float* __restrict__ V, float* __restrict__ O, float scale)
{
    constexpr int SSTR = 260;
    extern __shared__ char smraw[];
    __half2* Ssm    = (__half2*)(smraw);
    __half2* Qs2    = (__half2*)(smraw + 64*SSTR*4);
    __half2* Ks2    = (__half2*)(smraw + 64*SSTR*4 + 64*36*4);
    __half2* Vs2    = (__half2*)(smraw + 64*SSTR*4 + 2*64*36*4);
    float*   rowInv = (float*)  (smraw + 64*SSTR*4 + 2*64*36*4 + 16*72*4);

    const int bh = blockIdx.y;
    const int b  = bh >> 4, h = bh & 15;
    const int q0 = (gridDim.x - 1 - blockIdx.x) * 64;   // heavy blocks first
    const int tid  = threadIdx.x;
    const int warp = tid >> 5, lane = tid & 31;
    const int g = lane >> 2, tig = lane & 3;
    const int wm = warp >> 2;
    const int wn = warp & 3;

    const int kend = q0 + 64;
    const int r4 = tid >> 2, c4 = tid & 3;

    const float* Kbase = K + ((size_t)b*cSQ)*cD + h*cDK;
    const float* Vbase = V + ((size_t)b*cSQ)*cD + h*cDK;

    float4 pk0, pk1, pk2, pk3;
    auto ldgK = [&](int kt) {
        const float* kp = Kbase + (size_t)(kt*64 + r4)*cD + c4*16;
        pk0 = *(const float4*)(kp);     pk1 = *(const float4*)(kp + 4);
        pk2 = *(const float4*)(kp + 8); pk3 = *(const float4*)(kp + 12);
    };
    auto stsK = [&]() {
        *(uint4*)&Ks2[r4*36 + c4*8]     = pack8(pk0, pk1);
        *(uint4*)&Ks2[r4*36 + c4*8 + 4] = pack8(pk2, pk3);
    };

    ldgK(0);

    {
        const float* qp = Q + ((size_t)b*cSQ + q0 + r4)*cD + h*cDK + c4*16;
        float4 v0 = *(const float4*)(qp),     v1 = *(const float4*)(qp + 4);
        float4 v2 = *(const float4*)(qp + 8), v3 = *(const float4*)(qp + 12);
        *(uint4*)&Qs2[r4*36 + c4*8]     = pack8(v0, v1);
        *(uint4*)&Qs2[r4*36 + c4*8 + 4] = pack8(v2, v3);
    }

    const int nkt = kend >> 6;
    for (int kt = 0; kt < nkt; kt++) {
        stsK();
        __syncthreads();
        if (kt + 1 < nkt) ldgK(kt + 1);

        const int k0 = kt << 6;
        float acc[2][2][4] = {};
#pragma unroll
        for (int kk2 = 0; kk2 < 32; kk2 += 8) {
            uint32_t af[2][4];
#pragma unroll
            for (int mt = 0; mt < 2; mt++) {
                int r0 = wm*32 + mt*16 + g;
                af[mt][0] = *(const uint32_t*)&Qs2[r0*36 + kk2 + tig];
                af[mt][1] = *(const uint32_t*)&Qs2[(r0 + 8)*36 + kk2 + tig];
                af[mt][2] = *(const uint32_t*)&Qs2[r0*36 + kk2 + 4 + tig];
                af[mt][3] = *(const uint32_t*)&Qs2[(r0 + 8)*36 + kk2 + 4 + tig];
            }
            uint32_t bf[2][2];
#pragma unroll
            for (int nt = 0; nt < 2; nt++) {
                int n = wn*16 + nt*8 + g;
                bf[nt][0] = *(const uint32_t*)&Ks2[n*36 + kk2 + tig];
                bf[nt][1] = *(const uint32_t*)&Ks2[n*36 + kk2 + 4 + tig];
            }
#pragma unroll
            for (int mt = 0; mt < 2; mt++)
#pragma unroll
                for (int nt = 0; nt < 2; nt++)
                    mma_f16(acc[mt][nt], af[mt][0], af[mt][1], af[mt][2], af[mt][3],
                            bf[nt][0], bf[nt][1]);
        }

#pragma unroll
        for (int mt = 0; mt < 2; mt++) {
#pragma unroll
            for (int nt = 0; nt < 2; nt++) {
                int qr = wm*32 + mt*16 + g;
                int kg = k0 + wn*16 + nt*8 + 2*tig;
#pragma unroll
                for (int rr = 0; rr < 2; rr++) {
                    int q = q0 + qr + rr*8;
                    float v0 = acc[mt][nt][rr*2 + 0] * scale;
                    float v1 = acc[mt][nt][rr*2 + 1] * scale;
                    if (kg     > q) v0 = -INFINITY;
                    if (kg + 1 > q) v1 = -INFINITY;
                    Ssm[(qr + rr*8)*SSTR + (kg >> 1)] = __floats2half2_rn(v0, v1);
                }
            }
        }
        __syncthreads();
    }

    const int vk2 = tid >> 4, vd = (tid & 15) << 2;
    float4 pv0, pv1;
    auto ldgV = [&](int t) {
        const float* vp = Vbase + (size_t)(t*32 + 2*vk2)*cD + vd;
        pv0 = *(const float4*)vp;
        pv1 = *(const float4*)(vp + cD);
    };
    auto stsV = [&]() {
        *(uint4*)&Vs2[vk2*72 + vd] = make_uint4(
            h2u(__floats2half2_rn(pv0.x, pv1.x)), h2u(__floats2half2_rn(pv0.y, pv1.y)),
            h2u(__floats2half2_rn(pv0.z, pv1.z)), h2u(__floats2half2_rn(pv0.w, pv1.w)));
    };

    ldgV(0);

    // ---- softmax: exp to smem (raw), rowInv only (no normalize pass) ----
    const int kext2 = kend >> 1;
    {
        const int row = tid >> 2, qg = tid & 3;
        float m = -INFINITY;
        for (int i = qg; i < kext2; i += 4) {
            float2 f = __half22float2(Ssm[row*SSTR + i]);
            m = fmaxf(m, fmaxf(f.x, f.y));
        }
        m = fmaxf(m, __shfl_xor_sync(0xffffffffu, m, 1));
        m = fmaxf(m, __shfl_xor_sync(0xffffffffu, m, 2));

        float s = 0.f;
        for (int i = qg; i < kext2; i += 4) {
            float2 f = __half22float2(Ssm[row*SSTR + i]);
            float e0 = __expf(f.x - m), e1 = __expf(f.y - m);
            s += e0 + e1;
            Ssm[row*SSTR + i] = __floats2half2_rn(e0, e1);
        }
        s += __shfl_xor_sync(0xffffffffu, s, 1);
        s += __shfl_xor_sync(0xffffffffu, s, 2);
        if (qg == 0) rowInv[row] = 1.0f / s;
    }
    __syncthreads();

    // ---- A@V phase (on raw exp) ----
    float acc[2][2][4] = {};
    const int nvt = kend >> 5;
    for (int t = 0; t < nvt; t++) {
        stsV();
        __syncthreads();
        if (t + 1 < nvt) ldgV(t + 1);

        const int kb = t << 4;
#pragma unroll
        for (int c = 0; c < 2; c++) {
            uint32_t af[2][4];
#pragma unroll
            for (int mt = 0; mt < 2; mt++) {
                int r0 = wm*32 + mt*16 + g;
                af[mt][0] = *(const uint32_t*)&Ssm[r0*SSTR + kb + 8*c + tig];
                af[mt][1] = *(const uint32_t*)&Ssm[(r0 + 8)*SSTR + kb + 8*c + tig];
                af[mt][2] = *(const uint32_t*)&Ssm[r0*SSTR + kb + 8*c + 4 + tig];
                af[mt][3] = *(const uint32_t*)&Ssm[(r0 + 8)*SSTR + kb + 8*c + 4 + tig];
            }
            uint32_t bf[2][2];
#pragma unroll
            for (int nt = 0; nt < 2; nt++) {
                int n = wn*16 + nt*8 + g;
                bf[nt][0] = *(const uint32_t*)&Vs2[(8*c + tig)*72 + n];
                bf[nt][1] = *(const uint32_t*)&Vs2[(8*c + 4 + tig)*72 + n];
            }
#pragma unroll
            for (int mt = 0; mt < 2; mt++)
#pragma unroll
                for (int nt = 0; nt < 2; nt++)
                    mma_f16(acc[mt][nt], af[mt][0], af[mt][1], af[mt][2], af[mt][3],
                            bf[nt][0], bf[nt][1]);
        }
        __syncthreads();
    }

#pragma unroll
    for (int mt = 0; mt < 2; mt++) {
#pragma unroll
        for (int nt = 0; nt < 2; nt++) {
            int qr = wm*32 + mt*16 + g;
            int d  = wn*16 + nt*8 + 2*tig;
#pragma unroll
            for (int rr = 0; rr < 2; rr++) {
                const float inv = rowInv[qr + rr*8];
                size_t row = (size_t)b*cSQ + q0 + qr + rr*8;
                float2 v = { acc[mt][nt][rr*2 + 0] * inv, acc[mt][nt][rr*2 + 1] * inv };
                *(float2*)&O[row*cD + h*cDK + d] = v;
            }
        }
    }
}
constexpr int SMEM_SELF = 64*260*4 + 2*(64*36*4) + 16*72*4 + 256;   // 89856

// ---------------------------------------------------------------------------
// Fused CROSS attention: 32 q-rows/block, kv-mask, K/V register prefetch.
// Softmax stores raw exp; P writeout interleaved into the AV loop (fp32
// scaled -> P precision identical to before); AV epilogue scales by rowInv.
// ---------------------------------------------------------------------------
__global__ __launch_bounds__(256) void attn_cross_fused(
    const float* __restrict__ Q, const float* __restrict__ K,
    const float* __restrict__ V, const int* __restrict__ kvmask,
    float* __restrict__ P, float* __restrict__ O, float scale)
{
    constexpr int SSTR = 516;
    constexpr int SK = cSK;
    extern __shared__ char smraw[];
    __half2* Ssm    = (__half2*)(smraw);
    __half2* Qs2    = (__half2*)(smraw + 32*SSTR*4);
    __half2* Ks2    = (__half2*)(smraw + 32*SSTR*4 + 32*36*4);
    __half2* Vs2    = (__half2*)(smraw + 32*SSTR*4 + 32*36*4 + 64*36*4);
    int*     msk    = (int*)    (smraw + 32*SSTR*4 + 32*36*4 + 64*36*4 + 16*72*4);
    float*   rowInv = (float*)  (smraw + 32*SSTR*4 + 32*36*4 + 64*36*4 + 16*72*4 + 4096);

    const int bh = blockIdx.y;
    const int b  = bh >> 4, h = bh & 15;
    const int q0 = blockIdx.x * 32;
    const int tid  = threadIdx.x;
    const int warp = tid >> 5, lane = tid & 31;
    const int g = lane >> 2, tig = lane & 3;
    const int wm = warp >> 2;
    const int wn = warp & 3;

    const int r4 = tid >> 2, c4 = tid & 3;
    const float* Kbase = K + ((size_t)b*SK)*cD + h*cDK;
    const float* Vbase = V + ((size_t)b*SK)*cD + h*cDK;

    float4 pk0, pk1, pk2, pk3;
    auto ldgK = [&](int kt) {
        const float* kp = Kbase + (size_t)(kt*64 + r4)*cD + c4*16;
        pk0 = *(const float4*)(kp);     pk1 = *(const float4*)(kp + 4);
        pk2 = *(const float4*)(kp + 8); pk3 = *(const float4*)(kp + 12);
    };
    auto stsK = [&]() {
        *(uint4*)&Ks2[r4*36 + c4*8]     = pack8(pk0, pk1);
        *(uint4*)&Ks2[r4*36 + c4*8 + 4] = pack8(pk2, pk3);
    };

    ldgK(0);

    {
        const int r = tid >> 3, cq = tid & 7;
        const float* qp = Q + ((size_t)b*cSQ + q0 + r)*cD + h*cDK + cq*8;
        float4 v0 = *(const float4*)(qp), v1 = *(const float4*)(qp + 4);
        *(uint4*)&Qs2[r*36 + cq*4] = pack8(v0, v1);
    }
    for (int i = tid; i < SK; i += 256) msk[i] = kvmask[b*SK + i];

    const int nkt = SK >> 6;
    for (int kt = 0; kt < nkt; kt++) {
        stsK();
        __syncthreads();
        if (kt + 1 < nkt) ldgK(kt + 1);

        const int k0 = kt << 6;
        float acc[2][4] = {};
#pragma unroll
        for (int kk2 = 0; kk2 < 32; kk2 += 8) {
            uint32_t af[4];
            {
                int r0 = wm*16 + g;
                af[0] = *(const uint32_t*)&Qs2[r0*36 + kk2 + tig];
                af[1] = *(const uint32_t*)&Qs2[(r0 + 8)*36 + kk2 + tig];
                af[2] = *(const uint32_t*)&Qs2[r0*36 + kk2 + 4 + tig];
                af[3] = *(const uint32_t*)&Qs2[(r0 + 8)*36 + kk2 + 4 + tig];
            }
            uint32_t bf[2][2];
#pragma unroll
            for (int nt = 0; nt < 2; nt++) {
                int n = wn*16 + nt*8 + g;
                bf[nt][0] = *(const uint32_t*)&Ks2[n*36 + kk2 + tig];
                bf[nt][1] = *(const uint32_t*)&Ks2[n*36 + kk2 + 4 + tig];
            }
#pragma unroll
            for (int nt = 0; nt < 2; nt++)
                mma_f16(acc[nt], af[0], af[1], af[2], af[3], bf[nt][0], bf[nt][1]);
        }

#pragma unroll
        for (int nt = 0; nt < 2; nt++) {
            int qr = wm*16 + g;
            int kg = k0 + wn*16 + nt*8 + 2*tig;
            bool m0 = msk[kg] == 0;
            bool m1 = msk[kg + 1] == 0;
#pragma unroll
            for (int rr = 0; rr < 2; rr++) {
                float v0 = m0 ? -INFINITY : acc[nt][rr*2 + 0] * scale;
                float v1 = m1 ? -INFINITY : acc[nt][rr*2 + 1] * scale;
                Ssm[(qr + rr*8)*SSTR + (kg >> 1)] = __floats2half2_rn(v0, v1);
            }
        }
        __syncthreads();
    }

    const int vk2 = tid >> 4, vd = (tid & 15) << 2;
    float4 pv0, pv1;
    auto ldgV = [&](int t) {
        const float* vp = Vbase + (size_t)(t*32 + 2*vk2)*cD + vd;
        pv0 = *(const float4*)vp;
        pv1 = *(const float4*)(vp + cD);
    };
    auto stsV = [&]() {
        *(uint4*)&Vs2[vk2*72 + vd] = make_uint4(
            h2u(__floats2half2_rn(pv0.x, pv1.x)), h2u(__floats2half2_rn(pv0.y, pv1.y)),
            h2u(__floats2half2_rn(pv0.z, pv1.z)), h2u(__floats2half2_rn(pv0.w, pv1.w)));
    };

    ldgV(0);

    // ---- softmax: exp to smem (raw), rowInv only ----
    constexpr int kext2 = SK >> 1;
    {
        const int row = tid >> 3, l8 = tid & 7;
        float m = -INFINITY;
        for (int i = l8; i < kext2; i += 8) {
            float2 f = __half22float2(Ssm[row*SSTR + i]);
            m = fmaxf(m, fmaxf(f.x, f.y));
        }
        m = fmaxf(m, __shfl_xor_sync(0xffffffffu, m, 1));
        m = fmaxf(m, __shfl_xor_sync(0xffffffffu, m, 2));
        m = fmaxf(m, __shfl_xor_sync(0xffffffffu, m, 4));

        float s = 0.f;
        for (int i = l8; i < kext2; i += 8) {
            float2 f = __half22float2(Ssm[row*SSTR + i]);
            float e0 = __expf(f.x - m), e1 = __expf(f.y - m);
            s += e0 + e1;
            Ssm[row*SSTR + i] = __floats2half2_rn(e0, e1);
        }
        s += __shfl_xor_sync(0xffffffffu, s, 1);
        s += __shfl_xor_sync(0xffffffffu, s, 2);
        s += __shfl_xor_sync(0xffffffffu, s, 4);
        if (l8 == 0) rowInv[row] = 1.0f / s;
    }
    __syncthreads();

    // ---- A@V phase with interleaved P writeout ----
    float acc[2][4] = {};
    const int nvt = SK >> 5;                // 32 iterations
    constexpr int PCH = kext2 / 32;         // 16 half2 columns per iteration
    const int pcol = lane & 15;             // 0..15
    const int prsub = lane >> 4;            // 0..1
    for (int t = 0; t < nvt; t++) {
        stsV();
        __syncthreads();
        if (t + 1 < nvt) ldgV(t + 1);

        // P chunk for this iteration: columns [t*PCH, (t+1)*PCH), 4 rows/warp.
        {
            const int i = t*PCH + pcol;
#pragma unroll
            for (int rr = 0; rr < 2; rr++) {
                const int r = warp + (rr*2 + prsub)*8;     // {0..31}
                float2 f = __half22float2(Ssm[r*SSTR + i]);
                const float inv = rowInv[r];
                f.x *= inv; f.y *= inv;
                *(float2*)&P[((size_t)bh*cSQ + q0 + r)*SK + 2*i] = f;
            }
        }

        const int kb = t << 4;
#pragma unroll
        for (int c = 0; c < 2; c++) {
            uint32_t af[4];
            {
                int r0 = wm*16 + g;
                af[0] = *(const uint32_t*)&Ssm[r0*SSTR + kb + 8*c + tig];
                af[1] = *(const uint32_t*)&Ssm[(r0 + 8)*SSTR + kb + 8*c + tig];
                af[2] = *(const uint32_t*)&Ssm[r0*SSTR + kb + 8*c + 4 + tig];
                af[3] = *(const uint32_t*)&Ssm[(r0 + 8)*SSTR + kb + 8*c + 4 + tig];
            }
            uint32_t bf[2][2];
#pragma unroll
            for (int nt = 0; nt < 2; nt++) {
                int n = wn*16 + nt*8 + g;
                bf[nt][0] = *(const uint32_t*)&Vs2[(8*c + tig)*72 + n];
                bf[nt][1] = *(const uint32_t*)&Vs2[(8*c + 4 + tig)*72 + n];
            }
#pragma unroll
            for (int nt = 0; nt < 2; nt++)
                mma_f16(acc[nt], af[0], af[1], af[2], af[3], bf[nt][0], bf[nt][1]);
        }
        __syncthreads();
    }

#pragma unroll
    for (int nt = 0; nt < 2; nt++) {
        int qr = wm*16 + g;
        int d  = wn*16 + nt*8 + 2*tig;
#pragma unroll
        for (int rr = 0; rr < 2; rr++) {
            const float inv = rowInv[qr + rr*8];
            size_t row = (size_t)b*cSQ + q0 + qr + rr*8;
            float2 v = { acc[nt][rr*2 + 0] * inv, acc[nt][rr*2 + 1] * inv };
            *(float2*)&O[row*cD + h*cDK + d] = v;
        }
    }
}
constexpr int SMEM_CROSS = 32*516*4 + 32*36*4 + 64*36*4 + 16*72*4 + 4096 + 128;  // 88704

// ---------------------------------------------------------------------------
// out = LayerNorm(X + R) * g + b, D=1024. Shuffle reductions, 2 syncs.
// ---------------------------------------------------------------------------
__global__ __launch_bounds__(256) void ln_residual_kernel(
    const float* __restrict__ X, const float* __restrict__ R,
    const float* __restrict__ g, const float* __restrict__ be,
    float* __restrict__ out)
{
    __shared__ float redm[8];
    __shared__ float redv[8];
    const size_t row = blockIdx.x;
    const int t = threadIdx.x;
    const int warp = t >> 5, lane = t & 31;
    const float* xr = X + row*cD;
    const float* rr = R + row*cD;

    float v[4]; float s = 0.f;
#pragma unroll
    for (int i = 0; i < 4; i++) { v[i] = xr[t + i*256] + rr[t + i*256]; s += v[i]; }
#pragma unroll
    for (int off = 16; off > 0; off >>= 1)
        s += __shfl_xor_sync(0xffffffffu, s, off);
    if (lane == 0) redm[warp] = s;
    __syncthreads();
    float mu = redm[0];
#pragma unroll
    for (int i = 1; i < 8; i++) mu += redm[i];
    mu *= (1.0f / cD);

    float vs = 0.f;
#pragma unroll
    for (int i = 0; i < 4; i++) { float d = v[i] - mu; vs += d*d; }
#pragma unroll
    for (int off = 16; off > 0; off >>= 1)
        vs += __shfl_xor_sync(0xffffffffu, vs, off);
    if (lane == 0) redv[warp] = vs;
    __syncthreads();
    float var = redv[0];
#pragma unroll
    for (int i = 1; i < 8; i++) var += redv[i];
    float inv = rsqrtf(var * (1.0f / cD) + 1e-5f);

    float* orow = out + row*cD;
#pragma unroll
    for (int i = 0; i < 4; i++) {
        int c = t + i*256;
        orow[c] = (v[i] - mu) * inv * g[c] + be[c];
    }
}

// ---------------------------------------------------------------------------
// Side-stream handles (created lazily once; host-side only, no device mem)
// ---------------------------------------------------------------------------
static cudaStream_t g_s2 = nullptr;
static cudaEvent_t  g_evFork = nullptr, g_evJoin = nullptr;

// ---------------------------------------------------------------------------
// Launch
// ---------------------------------------------------------------------------
extern "C" void kernel_launch(void* const* d_in, const int* in_sizes, int n_in,
                              void* d_out, int out_size)
{
    const float* x        = (const float*)d_in[0];
    const float* enc_o    = (const float*)d_in[1];
    const int*   enc_mask = (const int*)  d_in[2];
    const float* a1_wq = (const float*)d_in[3];
    const float* a1_bq = (const float*)d_in[4];
    const float* a1_wk = (const float*)d_in[5];
    const float* a1_bk = (const float*)d_in[6];
    const float* a1_wv = (const float*)d_in[7];
    const float* a1_bv = (const float*)d_in[8];
    const float* a1_wo = (const float*)d_in[9];
    const float* a1_bo = (const float*)d_in[10];
    const float* a2_wq = (const float*)d_in[11];
    const float* a2_bq = (const float*)d_in[12];
    const float* a2_wk = (const float*)d_in[13];
    const float* a2_bk = (const float*)d_in[14];
    const float* a2_wv = (const float*)d_in[15];
    const float* a2_bv = (const float*)d_in[16];
    const float* a2_wo = (const float*)d_in[17];
    const float* a2_bo = (const float*)d_in[18];
    const float* ff_w1 = (const float*)d_in[19];
    const float* ff_b1 = (const float*)d_in[20];
    const float* ff_w2 = (const float*)d_in[21];
    const float* ff_b2 = (const float*)d_in[22];
    const float* ln1_g = (const float*)d_in[23];
    const float* ln1_b = (const float*)d_in[24];
    const float* ln2_g = (const float*)d_in[25];
    const float* ln2_b = (const float*)d_in[26];
    const float* ln3_g = (const float*)d_in[27];
    const float* ln3_b = (const float*)d_in[28];

    float* out_x    = (float*)d_out;
    float* out_attn = out_x + (size_t)cB*cSQ*cD;

    float *bufQ, *bufK, *bufV, *bufK2, *bufV2, *bufC, *bufO, *bufX1, *bufX2, *bufF;
    cudaGetSymbolAddress((void**)&bufQ,  g_bufQ);
    cudaGetSymbolAddress((void**)&bufK,  g_bufK);
    cudaGetSymbolAddress((void**)&bufV,  g_bufV);
    cudaGetSymbolAddress((void**)&bufK2, g_bufK2);
    cudaGetSymbolAddress((void**)&bufV2, g_bufV2);
    cudaGetSymbolAddress((void**)&bufC,  g_bufC);
    cudaGetSymbolAddress((void**)&bufO,  g_bufO);
    cudaGetSymbolAddress((void**)&bufX1, g_bufX1);
    cudaGetSymbolAddress((void**)&bufX2, g_bufX2);
    cudaGetSymbolAddress((void**)&bufF,  g_bufF);

    if (g_s2 == nullptr) {
        cudaStreamCreateWithFlags(&g_s2, cudaStreamNonBlocking);
        cudaEventCreateWithFlags(&g_evFork, cudaEventDisableTiming);
        cudaEventCreateWithFlags(&g_evJoin, cudaEventDisableTiming);
    }

    cudaFuncSetAttribute(attn_self_fused,
                         cudaFuncAttributeMaxDynamicSharedMemorySize, SMEM_SELF);
    cudaFuncSetAttribute(attn_cross_fused,
                         cudaFuncAttributeMaxDynamicSharedMemorySize, SMEM_CROSS);

    const float scale = 0.125f;   // 1/sqrt(64)
    const dim3 blk(256);
    const int M1 = cB * cSQ;      // 4096
    const int M2 = cB * cSK;      // 8192

    // ---- fork: cross K/V projection (depends only on enc_o) on side stream
    cudaEventRecord(g_evFork, 0);
    cudaStreamWaitEvent(g_s2, g_evFork, 0);
    gemm_fp16<false><<<dim3(cD/128, M2/128, 2), blk, 0, g_s2>>>(
        enc_o, mkset(a2_wk, a2_bk, bufK2, a2_wv, a2_bv, bufV2), M2, cD, cD);
    cudaEventRecord(g_evJoin, g_s2);

    // ---- main stream: self-attention block ----
    gemm_fp16<false><<<dim3(cD/128, M1/128, 3), blk>>>(
        x, mkset(a1_wq, a1_bq, bufQ, a1_wk, a1_bk, bufK, a1_wv, a1_bv, bufV),
        M1, cD, cD);
    attn_self_fused<<<dim3(cSQ/64, cB*cH), blk, SMEM_SELF>>>(
        bufQ, bufK, bufV, bufC, scale);
    gemm_fp16<false><<<dim3(cD/128, M1/128, 1), blk>>>(
        bufC, mkset(a1_wo, a1_bo, bufO), M1, cD, cD);
    ln_residual_kernel<<<M1, blk>>>(x, bufO, ln1_g, ln1_b, bufX1);

    // ---- cross-attention block ----
    gemm_fp16<false><<<dim3(cD/128, M1/128, 1), blk>>>(
        bufX1, mkset(a2_wq, a2_bq, bufQ), M1, cD, cD);
    cudaStreamWaitEvent(0, g_evJoin, 0);    // join side stream
    attn_cross_fused<<<dim3(cSQ/32, cB*cH), blk, SMEM_CROSS>>>(
        bufQ, bufK2, bufV2, enc_mask, out_attn, bufC, scale);
    gemm_fp16<false><<<dim3(cD/128, M1/128, 1), blk>>>(
        bufC, mkset(a2_wo, a2_bo, bufO), M1, cD, cD);
    ln_residual_kernel<<<M1, blk>>>(bufX1, bufO, ln2_g, ln2_b, bufX2);

    // ---- feed-forward ----
    gemm_fp16<true ><<<dim3(cF/128, M1/128, 1), blk>>>(
        bufX2, mkset(ff_w1, ff_b1, bufF), M1, cF, cD);
    gemm_fp16<false><<<dim3(cD/128, M1/128, 1), blk>>>(
        bufF, mkset(ff_w2, ff_b2, bufO), M1, cD, cF);
    ln_residual_kernel<<<M1, blk>>>(bufX2, bufO, ln3_g, ln3_b, out_x);
}

// round 16
// speedup vs baseline: 1.0307x; 1.0307x over previous
#include <cuda_runtime.h>
#include <cuda_fp16.h>
#include <math.h>
#include <stdint.h>

// Problem constants
constexpr int cB  = 8;
constexpr int cSQ = 512;
constexpr int cSK = 1024;
constexpr int cD  = 1024;
constexpr int cH  = 16;
constexpr int cDK = 64;
constexpr int cF  = 4096;

// ---------------------------------------------------------------------------
// Scratch (device globals; no allocations allowed)
// ---------------------------------------------------------------------------
__device__ float g_bufQ [(size_t)cB*cSQ*cD];
__device__ float g_bufK [(size_t)cB*cSQ*cD];    // self K
__device__ float g_bufV [(size_t)cB*cSQ*cD];    // self V
__device__ float g_bufK2[(size_t)cB*cSK*cD];    // cross K
__device__ float g_bufV2[(size_t)cB*cSK*cD];    // cross V
__device__ float g_bufC [(size_t)cB*cSQ*cD];
__device__ float g_bufO [(size_t)cB*cSQ*cD];
__device__ float g_bufX1[(size_t)cB*cSQ*cD];
__device__ float g_bufX2[(size_t)cB*cSQ*cD];
__device__ float g_bufF [(size_t)cB*cSQ*cF];

// ---------------------------------------------------------------------------
// helpers
// ---------------------------------------------------------------------------
__device__ __forceinline__ void mma_f16(float c[4],
    uint32_t a0, uint32_t a1, uint32_t a2, uint32_t a3,
    uint32_t b0, uint32_t b1)
{
    asm volatile(
        "mma.sync.aligned.m16n8k16.row.col.f32.f16.f16.f32 "
        "{%0,%1,%2,%3}, {%4,%5,%6,%7}, {%8,%9}, {%0,%1,%2,%3};"
        : "+f"(c[0]), "+f"(c[1]), "+f"(c[2]), "+f"(c[3])
        : "r"(a0), "r"(a1), "r"(a2), "r"(a3), "r"(b0), "r"(b1));
}

__device__ __forceinline__ uint32_t h2u(__half2 h) {
    return *reinterpret_cast<uint32_t*>(&h);
}

__device__ __forceinline__ uint4 pack8(float4 a, float4 b) {
    return make_uint4(
        h2u(__floats2half2_rn(a.x, a.y)), h2u(__floats2half2_rn(a.z, a.w)),
        h2u(__floats2half2_rn(b.x, b.y)), h2u(__floats2half2_rn(b.z, b.w)));
}

// Pointer set for multi-output GEMM (blockIdx.z selects)
struct GemmSet {
    const float* W[3];
    const float* bias[3];
    float*       C[3];
};

// ---------------------------------------------------------------------------
// fp16 GEMM (proven body): C[M,N] = A[M,K] @ W[K,N] + bias (+ReLU).
// ---------------------------------------------------------------------------
template<bool RELU>
__global__ __launch_bounds__(256, 2) void gemm_fp16(
    const float* __restrict__ A, GemmSet set,
    int M, int N, int K)
{
    const float* __restrict__ W    = set.W[blockIdx.z];
    const float* __restrict__ bias = set.bias[blockIdx.z];
    float* __restrict__       C    = set.C[blockIdx.z];

    __shared__ __half2 As2[128 * 12];
    __shared__ __half2 Bs2[8 * 136];

    const int tid  = threadIdx.x;
    const int bx   = blockIdx.x, by = blockIdx.y;
    const int warp = tid >> 5, lane = tid & 31;
    const int g = lane >> 2, tig = lane & 3;
    const int wm = warp >> 2;
    const int wn = warp & 3;

    const int ar  = tid >> 1;
    const int ac2 = (tid & 1) * 4;
    const float* Asrc = A + (size_t)(by*128 + ar)*K + ac2*2;

    const int bk2 = warp;
    const int bn  = lane * 4;
    const float* Bsrc0 = W + (size_t)(2*bk2    )*N + bx*128 + bn;
    const float* Bsrc1 = W + (size_t)(2*bk2 + 1)*N + bx*128 + bn;

    const int nk = K >> 4;
    float acc[4][4][4] = {};

    float4 pa0 = *(const float4*)(Asrc);
    float4 pa1 = *(const float4*)(Asrc + 4);
    float4 pb0 = *(const float4*)(Bsrc0);
    float4 pb1 = *(const float4*)(Bsrc1);

    for (int kt = 0; kt < nk; kt++) {
        {
            *(uint4*)&As2[ar*12 + ac2] = pack8(pa0, pa1);
            __half2 b0 = __floats2half2_rn(pb0.x, pb1.x);
            __half2 b1 = __floats2half2_rn(pb0.y, pb1.y);
            __half2 b2 = __floats2half2_rn(pb0.z, pb1.z);
            __half2 b3 = __floats2half2_rn(pb0.w, pb1.w);
            *(uint4*)&Bs2[bk2*136 + bn] = make_uint4(h2u(b0), h2u(b1), h2u(b2), h2u(b3));
        }
        __syncthreads();

        if (kt + 1 < nk) {
            const int kn = (kt + 1) << 4;
            pa0 = *(const float4*)(Asrc + kn);
            pa1 = *(const float4*)(Asrc + kn + 4);
            pb0 = *(const float4*)(Bsrc0 + (size_t)kn*N);
            pb1 = *(const float4*)(Bsrc1 + (size_t)kn*N);
        }

        uint32_t af[4][4];
#pragma unroll
        for (int mt = 0; mt < 4; mt++) {
            int r0 = wm*64 + mt*16 + g;
            af[mt][0] = *(uint32_t*)&As2[r0*12 + tig];
            af[mt][1] = *(uint32_t*)&As2[(r0 + 8)*12 + tig];
            af[mt][2] = *(uint32_t*)&As2[r0*12 + 4 + tig];
            af[mt][3] = *(uint32_t*)&As2[(r0 + 8)*12 + 4 + tig];
        }
        uint32_t bf[4][2];
#pragma unroll
        for (int nt = 0; nt < 4; nt++) {
            int n = wn*32 + nt*8 + g;
            bf[nt][0] = *(uint32_t*)&Bs2[tig*136 + n];
            bf[nt][1] = *(uint32_t*)&Bs2[(4 + tig)*136 + n];
        }
#pragma unroll
        for (int mt = 0; mt < 4; mt++)
#pragma unroll
            for (int nt = 0; nt < 4; nt++)
                mma_f16(acc[mt][nt], af[mt][0], af[mt][1], af[mt][2], af[mt][3],
                        bf[nt][0], bf[nt][1]);
        __syncthreads();
    }

#pragma unroll
    for (int mt = 0; mt < 4; mt++) {
#pragma unroll
        for (int nt = 0; nt < 4; nt++) {
            int row0 = by*128 + wm*64 + mt*16 + g;
            int col  = bx*128 + wn*32 + nt*8 + 2*tig;
            float b0 = bias[col], b1 = bias[col + 1];
            float2 v0 = { acc[mt][nt][0] + b0, acc[mt][nt][1] + b1 };
            float2 v1 = { acc[mt][nt][2] + b0, acc[mt][nt][3] + b1 };
            if (RELU) {
                v0.x = fmaxf(v0.x, 0.f); v0.y = fmaxf(v0.y, 0.f);
                v1.x = fmaxf(v1.x, 0.f); v1.y = fmaxf(v1.y, 0.f);
            }
            *(float2*)&C[(size_t)row0*N + col]       = v0;
            *(float2*)&C[(size_t)(row0 + 8)*N + col] = v1;
        }
    }
}

static inline GemmSet mkset(const float* w0, const float* b0, float* c0,
                            const float* w1 = nullptr, const float* b1 = nullptr, float* c1 = nullptr,
                            const float* w2 = nullptr, const float* b2 = nullptr, float* c2 = nullptr)
{
    GemmSet s;
    s.W[0] = w0; s.bias[0] = b0; s.C[0] = c0;
    s.W[1] = w1; s.bias[1] = b1; s.C[1] = c1;
    s.W[2] = w2; s.bias[2] = b2; s.C[2] = c2;
    return s;
}

// ---------------------------------------------------------------------------
// Fused SELF attention (causal): 64 q-rows/block, K/V register prefetch.
// Softmax stores raw exp + rowInv; AV on raw exp; epilogue scales (fp32).
// ---------------------------------------------------------------------------
__global__ __launch_bounds__(256) void attn_self_fused(
    const float* __restrict__ Q, const float* __restrict__ K,
    const float* __restrict__ V, float* __restrict__ O, float scale)
{
    constexpr int SSTR = 260;
    extern __shared__ char smraw[];
    __half2* Ssm    = (__half2*)(smraw);
    __half2* Qs2    = (__half2*)(smraw + 64*SSTR*4);
    __half2* Ks2    = (__half2*)(smraw + 64*SSTR*4 + 64*36*4);
    __half2* Vs2    = (__half2*)(smraw + 64*SSTR*4 + 2*64*36*4);
    float*   rowInv = (float*)  (smraw + 64*SSTR*4 + 2*64*36*4 + 16*72*4);

    const int bh = blockIdx.y;
    const int b  = bh >> 4, h = bh & 15;
    const int q0 = (gridDim.x - 1 - blockIdx.x) * 64;   // heavy blocks first
    const int tid  = threadIdx.x;
    const int warp = tid >> 5, lane = tid & 31;
    const int g = lane >> 2, tig = lane & 3;
    const int wm = warp >> 2;
    const int wn = warp & 3;

    const int kend = q0 + 64;
    const int r4 = tid >> 2, c4 = tid & 3;

    const float* Kbase = K + ((size_t)b*cSQ)*cD + h*cDK;
    const float* Vbase = V + ((size_t)b*cSQ)*cD + h*cDK;

    float4 pk0, pk1, pk2, pk3;
    auto ldgK = [&](int kt) {
        const float* kp = Kbase + (size_t)(kt*64 + r4)*cD + c4*16;
        pk0 = *(const float4*)(kp);     pk1 = *(const float4*)(kp + 4);
        pk2 = *(const float4*)(kp + 8); pk3 = *(const float4*)(kp + 12);
    };
    auto stsK = [&]() {
        *(uint4*)&Ks2[r4*36 + c4*8]     = pack8(pk0, pk1);
        *(uint4*)&Ks2[r4*36 + c4*8 + 4] = pack8(pk2, pk3);
    };

    ldgK(0);

    {
        const float* qp = Q + ((size_t)b*cSQ + q0 + r4)*cD + h*cDK + c4*16;
        float4 v0 = *(const float4*)(qp),     v1 = *(const float4*)(qp + 4);
        float4 v2 = *(const float4*)(qp + 8), v3 = *(const float4*)(qp + 12);
        *(uint4*)&Qs2[r4*36 + c4*8]     = pack8(v0, v1);
        *(uint4*)&Qs2[r4*36 + c4*8 + 4] = pack8(v2, v3);
    }

    const int nkt = kend >> 6;
    for (int kt = 0; kt < nkt; kt++) {
        stsK();
        __syncthreads();
        if (kt + 1 < nkt) ldgK(kt + 1);

        const int k0 = kt << 6;
        float acc[2][2][4] = {};
#pragma unroll
        for (int kk2 = 0; kk2 < 32; kk2 += 8) {
            uint32_t af[2][4];
#pragma unroll
            for (int mt = 0; mt < 2; mt++) {
                int r0 = wm*32 + mt*16 + g;
                af[mt][0] = *(const uint32_t*)&Qs2[r0*36 + kk2 + tig];
                af[mt][1] = *(const uint32_t*)&Qs2[(r0 + 8)*36 + kk2 + tig];
                af[mt][2] = *(const uint32_t*)&Qs2[r0*36 + kk2 + 4 + tig];
                af[mt][3] = *(const uint32_t*)&Qs2[(r0 + 8)*36 + kk2 + 4 + tig];
            }
            uint32_t bf[2][2];
#pragma unroll
            for (int nt = 0; nt < 2; nt++) {
                int n = wn*16 + nt*8 + g;
                bf[nt][0] = *(const uint32_t*)&Ks2[n*36 + kk2 + tig];
                bf[nt][1] = *(const uint32_t*)&Ks2[n*36 + kk2 + 4 + tig];
            }
#pragma unroll
            for (int mt = 0; mt < 2; mt++)
#pragma unroll
                for (int nt = 0; nt < 2; nt++)
                    mma_f16(acc[mt][nt], af[mt][0], af[mt][1], af[mt][2], af[mt][3],
                            bf[nt][0], bf[nt][1]);
        }

#pragma unroll
        for (int mt = 0; mt < 2; mt++) {
#pragma unroll
            for (int nt = 0; nt < 2; nt++) {
                int qr = wm*32 + mt*16 + g;
                int kg = k0 + wn*16 + nt*8 + 2*tig;
#pragma unroll
                for (int rr = 0; rr < 2; rr++) {
                    int q = q0 + qr + rr*8;
                    float v0 = acc[mt][nt][rr*2 + 0] * scale;
                    float v1 = acc[mt][nt][rr*2 + 1] * scale;
                    if (kg     > q) v0 = -INFINITY;
                    if (kg + 1 > q) v1 = -INFINITY;
                    Ssm[(qr + rr*8)*SSTR + (kg >> 1)] = __floats2half2_rn(v0, v1);
                }
            }
        }
        __syncthreads();
    }

    const int vk2 = tid >> 4, vd = (tid & 15) << 2;
    float4 pv0, pv1;
    auto ldgV = [&](int t) {
        const float* vp = Vbase + (size_t)(t*32 + 2*vk2)*cD + vd;
        pv0 = *(const float4*)vp;
        pv1 = *(const float4*)(vp + cD);
    };
    auto stsV = [&]() {
        *(uint4*)&Vs2[vk2*72 + vd] = make_uint4(
            h2u(__floats2half2_rn(pv0.x, pv1.x)), h2u(__floats2half2_rn(pv0.y, pv1.y)),
            h2u(__floats2half2_rn(pv0.z, pv1.z)), h2u(__floats2half2_rn(pv0.w, pv1.w)));
    };

    ldgV(0);

    // ---- softmax: raw exp to smem, rowInv only (no normalize pass) ----
    const int kext2 = kend >> 1;
    {
        const int row = tid >> 2, qg = tid & 3;
        float m = -INFINITY;
        for (int i = qg; i < kext2; i += 4) {
            float2 f = __half22float2(Ssm[row*SSTR + i]);
            m = fmaxf(m, fmaxf(f.x, f.y));
        }
        m = fmaxf(m, __shfl_xor_sync(0xffffffffu, m, 1));
        m = fmaxf(m, __shfl_xor_sync(0xffffffffu, m, 2));

        float s = 0.f;
        for (int i = qg; i < kext2; i += 4) {
            float2 f = __half22float2(Ssm[row*SSTR + i]);
            float e0 = __expf(f.x - m), e1 = __expf(f.y - m);
            s += e0 + e1;
            Ssm[row*SSTR + i] = __floats2half2_rn(e0, e1);
        }
        s += __shfl_xor_sync(0xffffffffu, s, 1);
        s += __shfl_xor_sync(0xffffffffu, s, 2);
        if (qg == 0) rowInv[row] = 1.0f / s;
    }
    __syncthreads();

    // ---- A@V phase (raw exp) ----
    float acc[2][2][4] = {};
    const int nvt = kend >> 5;
    for (int t = 0; t < nvt; t++) {
        stsV();
        __syncthreads();
        if (t + 1 < nvt) ldgV(t + 1);

        const int kb = t << 4;
#pragma unroll
        for (int c = 0; c < 2; c++) {
            uint32_t af[2][4];
#pragma unroll
            for (int mt = 0; mt < 2; mt++) {
                int r0 = wm*32 + mt*16 + g;
                af[mt][0] = *(const uint32_t*)&Ssm[r0*SSTR + kb + 8*c + tig];
                af[mt][1] = *(const uint32_t*)&Ssm[(r0 + 8)*SSTR + kb + 8*c + tig];
                af[mt][2] = *(const uint32_t*)&Ssm[r0*SSTR + kb + 8*c + 4 + tig];
                af[mt][3] = *(const uint32_t*)&Ssm[(r0 + 8)*SSTR + kb + 8*c + 4 + tig];
            }
            uint32_t bf[2][2];
#pragma unroll
            for (int nt = 0; nt < 2; nt++) {
                int n = wn*16 + nt*8 + g;
                bf[nt][0] = *(const uint32_t*)&Vs2[(8*c + tig)*72 + n];
                bf[nt][1] = *(const uint32_t*)&Vs2[(8*c + 4 + tig)*72 + n];
            }
#pragma unroll
            for (int mt = 0; mt < 2; mt++)
#pragma unroll
                for (int nt = 0; nt < 2; nt++)
                    mma_f16(acc[mt][nt], af[mt][0], af[mt][1], af[mt][2], af[mt][3],
                            bf[nt][0], bf[nt][1]);
        }
        __syncthreads();
    }

#pragma unroll
    for (int mt = 0; mt < 2; mt++) {
#pragma unroll
        for (int nt = 0; nt < 2; nt++) {
            int qr = wm*32 + mt*16 + g;
            int d  = wn*16 + nt*8 + 2*tig;
#pragma unroll
            for (int rr = 0; rr < 2; rr++) {
                const float inv = rowInv[qr + rr*8];
                size_t row = (size_t)b*cSQ + q0 + qr + rr*8;
                float2 v = { acc[mt][nt][rr*2 + 0] * inv, acc[mt][nt][rr*2 + 1] * inv };
                *(float2*)&O[row*cD + h*cDK + d] = v;
            }
        }
    }
}
constexpr int SMEM_SELF = 64*260*4 + 2*(64*36*4) + 16*72*4 + 256;   // 89856

// ---------------------------------------------------------------------------
// Fused CROSS attention: 32 q-rows/block, kv-mask, K/V register prefetch.
// Softmax stores raw exp + rowInv; dedicated coalesced P writeout pass
// (fp32 scaled, no smem write-back); AV on raw exp; epilogue scales.
// ---------------------------------------------------------------------------
__global__ __launch_bounds__(256) void attn_cross_fused(
    const float* __restrict__ Q, const float* __restrict__ K,
    const float* __restrict__ V, const int* __restrict__ kvmask,
    float* __restrict__ P, float* __restrict__ O, float scale)
{
    constexpr int SSTR = 516;
    constexpr int SK = cSK;
    extern __shared__ char smraw[];
    __half2* Ssm    = (__half2*)(smraw);
    __half2* Qs2    = (__half2*)(smraw + 32*SSTR*4);
    __half2* Ks2    = (__half2*)(smraw + 32*SSTR*4 + 32*36*4);
    __half2* Vs2    = (__half2*)(smraw + 32*SSTR*4 + 32*36*4 + 64*36*4);
    int*     msk    = (int*)    (smraw + 32*SSTR*4 + 32*36*4 + 64*36*4 + 16*72*4);
    float*   rowInv = (float*)  (smraw + 32*SSTR*4 + 32*36*4 + 64*36*4 + 16*72*4 + 4096);

    const int bh = blockIdx.y;
    const int b  = bh >> 4, h = bh & 15;
    const int q0 = blockIdx.x * 32;
    const int tid  = threadIdx.x;
    const int warp = tid >> 5, lane = tid & 31;
    const int g = lane >> 2, tig = lane & 3;
    const int wm = warp >> 2;
    const int wn = warp & 3;

    const int r4 = tid >> 2, c4 = tid & 3;
    const float* Kbase = K + ((size_t)b*SK)*cD + h*cDK;
    const float* Vbase = V + ((size_t)b*SK)*cD + h*cDK;

    float4 pk0, pk1, pk2, pk3;
    auto ldgK = [&](int kt) {
        const float* kp = Kbase + (size_t)(kt*64 + r4)*cD + c4*16;
        pk0 = *(const float4*)(kp);     pk1 = *(const float4*)(kp + 4);
        pk2 = *(const float4*)(kp + 8); pk3 = *(const float4*)(kp + 12);
    };
    auto stsK = [&]() {
        *(uint4*)&Ks2[r4*36 + c4*8]     = pack8(pk0, pk1);
        *(uint4*)&Ks2[r4*36 + c4*8 + 4] = pack8(pk2, pk3);
    };

    ldgK(0);

    {
        const int r = tid >> 3, cq = tid & 7;
        const float* qp = Q + ((size_t)b*cSQ + q0 + r)*cD + h*cDK + cq*8;
        float4 v0 = *(const float4*)(qp), v1 = *(const float4*)(qp + 4);
        *(uint4*)&Qs2[r*36 + cq*4] = pack8(v0, v1);
    }
    for (int i = tid; i < SK; i += 256) msk[i] = kvmask[b*SK + i];

    const int nkt = SK >> 6;
    for (int kt = 0; kt < nkt; kt++) {
        stsK();
        __syncthreads();
        if (kt + 1 < nkt) ldgK(kt + 1);

        const int k0 = kt << 6;
        float acc[2][4] = {};
#pragma unroll
        for (int kk2 = 0; kk2 < 32; kk2 += 8) {
            uint32_t af[4];
            {
                int r0 = wm*16 + g;
                af[0] = *(const uint32_t*)&Qs2[r0*36 + kk2 + tig];
                af[1] = *(const uint32_t*)&Qs2[(r0 + 8)*36 + kk2 + tig];
                af[2] = *(const uint32_t*)&Qs2[r0*36 + kk2 + 4 + tig];
                af[3] = *(const uint32_t*)&Qs2[(r0 + 8)*36 + kk2 + 4 + tig];
            }
            uint32_t bf[2][2];
#pragma unroll
            for (int nt = 0; nt < 2; nt++) {
                int n = wn*16 + nt*8 + g;
                bf[nt][0] = *(const uint32_t*)&Ks2[n*36 + kk2 + tig];
                bf[nt][1] = *(const uint32_t*)&Ks2[n*36 + kk2 + 4 + tig];
            }
#pragma unroll
            for (int nt = 0; nt < 2; nt++)
                mma_f16(acc[nt], af[0], af[1], af[2], af[3], bf[nt][0], bf[nt][1]);
        }

#pragma unroll
        for (int nt = 0; nt < 2; nt++) {
            int qr = wm*16 + g;
            int kg = k0 + wn*16 + nt*8 + 2*tig;
            bool m0 = msk[kg] == 0;
            bool m1 = msk[kg + 1] == 0;
#pragma unroll
            for (int rr = 0; rr < 2; rr++) {
                float v0 = m0 ? -INFINITY : acc[nt][rr*2 + 0] * scale;
                float v1 = m1 ? -INFINITY : acc[nt][rr*2 + 1] * scale;
                Ssm[(qr + rr*8)*SSTR + (kg >> 1)] = __floats2half2_rn(v0, v1);
            }
        }
        __syncthreads();
    }

    const int vk2 = tid >> 4, vd = (tid & 15) << 2;
    float4 pv0, pv1;
    auto ldgV = [&](int t) {
        const float* vp = Vbase + (size_t)(t*32 + 2*vk2)*cD + vd;
        pv0 = *(const float4*)vp;
        pv1 = *(const float4*)(vp + cD);
    };
    auto stsV = [&]() {
        *(uint4*)&Vs2[vk2*72 + vd] = make_uint4(
            h2u(__floats2half2_rn(pv0.x, pv1.x)), h2u(__floats2half2_rn(pv0.y, pv1.y)),
            h2u(__floats2half2_rn(pv0.z, pv1.z)), h2u(__floats2half2_rn(pv0.w, pv1.w)));
    };

    ldgV(0);

    // ---- softmax: raw exp to smem, rowInv only ----
    constexpr int kext2 = SK >> 1;
    {
        const int row = tid >> 3, l8 = tid & 7;
        float m = -INFINITY;
        for (int i = l8; i < kext2; i += 8) {
            float2 f = __half22float2(Ssm[row*SSTR + i]);
            m = fmaxf(m, fmaxf(f.x, f.y));
        }
        m = fmaxf(m, __shfl_xor_sync(0xffffffffu, m, 1));
        m = fmaxf(m, __shfl_xor_sync(0xffffffffu, m, 2));
        m = fmaxf(m, __shfl_xor_sync(0xffffffffu, m, 4));

        float s = 0.f;
        for (int i = l8; i < kext2; i += 8) {
            float2 f = __half22float2(Ssm[row*SSTR + i]);
            float e0 = __expf(f.x - m), e1 = __expf(f.y - m);
            s += e0 + e1;
            Ssm[row*SSTR + i] = __floats2half2_rn(e0, e1);
        }
        s += __shfl_xor_sync(0xffffffffu, s, 1);
        s += __shfl_xor_sync(0xffffffffu, s, 2);
        s += __shfl_xor_sync(0xffffffffu, s, 4);
        if (l8 == 0) rowInv[row] = 1.0f / s;
    }
    __syncthreads();

    // ---- P writeout pass: warp per row, coalesced, fp32-scaled, read-only smem
#pragma unroll
    for (int r = warp; r < 32; r += 8) {
        const float inv = rowInv[r];
        float* Prow = &P[((size_t)bh*cSQ + q0 + r)*SK];
        for (int i = lane; i < kext2; i += 32) {
            float2 f = __half22float2(Ssm[r*SSTR + i]);
            f.x *= inv; f.y *= inv;
            *(float2*)&Prow[2*i] = f;
        }
    }
    // no __syncthreads needed: smem S unchanged; AV reads raw exp directly

    // ---- A@V phase (raw exp) ----
    float acc[2][4] = {};
    const int nvt = SK >> 5;
    for (int t = 0; t < nvt; t++) {
        stsV();
        __syncthreads();
        if (t + 1 < nvt) ldgV(t + 1);

        const int kb = t << 4;
#pragma unroll
        for (int c = 0; c < 2; c++) {
            uint32_t af[4];
            {
                int r0 = wm*16 + g;
                af[0] = *(const uint32_t*)&Ssm[r0*SSTR + kb + 8*c + tig];
                af[1] = *(const uint32_t*)&Ssm[(r0 + 8)*SSTR + kb + 8*c + tig];
                af[2] = *(const uint32_t*)&Ssm[r0*SSTR + kb + 8*c + 4 + tig];
                af[3] = *(const uint32_t*)&Ssm[(r0 + 8)*SSTR + kb + 8*c + 4 + tig];
            }
            uint32_t bf[2][2];
#pragma unroll
            for (int nt = 0; nt < 2; nt++) {
                int n = wn*16 + nt*8 + g;
                bf[nt][0] = *(const uint32_t*)&Vs2[(8*c + tig)*72 + n];
                bf[nt][1] = *(const uint32_t*)&Vs2[(8*c + 4 + tig)*72 + n];
            }
#pragma unroll
            for (int nt = 0; nt < 2; nt++)
                mma_f16(acc[nt], af[0], af[1], af[2], af[3], bf[nt][0], bf[nt][1]);
        }
        __syncthreads();
    }

#pragma unroll
    for (int nt = 0; nt < 2; nt++) {
        int qr = wm*16 + g;
        int d  = wn*16 + nt*8 + 2*tig;
#pragma unroll
        for (int rr = 0; rr < 2; rr++) {
            const float inv = rowInv[qr + rr*8];
            size_t row = (size_t)b*cSQ + q0 + qr + rr*8;
            float2 v = { acc[nt][rr*2 + 0] * inv, acc[nt][rr*2 + 1] * inv };
            *(float2*)&O[row*cD + h*cDK + d] = v;
        }
    }
}
constexpr int SMEM_CROSS = 32*516*4 + 32*36*4 + 64*36*4 + 16*72*4 + 4096 + 128;  // 88704

// ---------------------------------------------------------------------------
// out = LayerNorm(X + R) * g + b, D=1024. Shuffle reductions, 2 syncs.
// ---------------------------------------------------------------------------
__global__ __launch_bounds__(256) void ln_residual_kernel(
    const float* __restrict__ X, const float* __restrict__ R,
    const float* __restrict__ g, const float* __restrict__ be,
    float* __restrict__ out)
{
    __shared__ float redm[8];
    __shared__ float redv[8];
    const size_t row = blockIdx.x;
    const int t = threadIdx.x;
    const int warp = t >> 5, lane = t & 31;
    const float* xr = X + row*cD;
    const float* rr = R + row*cD;

    float v[4]; float s = 0.f;
#pragma unroll
    for (int i = 0; i < 4; i++) { v[i] = xr[t + i*256] + rr[t + i*256]; s += v[i]; }
#pragma unroll
    for (int off = 16; off > 0; off >>= 1)
        s += __shfl_xor_sync(0xffffffffu, s, off);
    if (lane == 0) redm[warp] = s;
    __syncthreads();
    float mu = redm[0];
#pragma unroll
    for (int i = 1; i < 8; i++) mu += redm[i];
    mu *= (1.0f / cD);

    float vs = 0.f;
#pragma unroll
    for (int i = 0; i < 4; i++) { float d = v[i] - mu; vs += d*d; }
#pragma unroll
    for (int off = 16; off > 0; off >>= 1)
        vs += __shfl_xor_sync(0xffffffffu, vs, off);
    if (lane == 0) redv[warp] = vs;
    __syncthreads();
    float var = redv[0];
#pragma unroll
    for (int i = 1; i < 8; i++) var += redv[i];
    float inv = rsqrtf(var * (1.0f / cD) + 1e-5f);

    float* orow = out + row*cD;
#pragma unroll
    for (int i = 0; i < 4; i++) {
        int c = t + i*256;
        orow[c] = (v[i] - mu) * inv * g[c] + be[c];
    }
}

// ---------------------------------------------------------------------------
// Side-stream handles (created lazily once; host-side only, no device mem)
// ---------------------------------------------------------------------------
static cudaStream_t g_s2 = nullptr;
static cudaEvent_t  g_evFork = nullptr, g_evJoin = nullptr;

// ---------------------------------------------------------------------------
// Launch
// ---------------------------------------------------------------------------
extern "C" void kernel_launch(void* const* d_in, const int* in_sizes, int n_in,
                              void* d_out, int out_size)
{
    const float* x        = (const float*)d_in[0];
    const float* enc_o    = (const float*)d_in[1];
    const int*   enc_mask = (const int*)  d_in[2];
    const float* a1_wq = (const float*)d_in[3];
    const float* a1_bq = (const float*)d_in[4];
    const float* a1_wk = (const float*)d_in[5];
    const float* a1_bk = (const float*)d_in[6];
    const float* a1_wv = (const float*)d_in[7];
    const float* a1_bv = (const float*)d_in[8];
    const float* a1_wo = (const float*)d_in[9];
    const float* a1_bo = (const float*)d_in[10];
    const float* a2_wq = (const float*)d_in[11];
    const float* a2_bq = (const float*)d_in[12];
    const float* a2_wk = (const float*)d_in[13];
    const float* a2_bk = (const float*)d_in[14];
    const float* a2_wv = (const float*)d_in[15];
    const float* a2_bv = (const float*)d_in[16];
    const float* a2_wo = (const float*)d_in[17];
    const float* a2_bo = (const float*)d_in[18];
    const float* ff_w1 = (const float*)d_in[19];
    const float* ff_b1 = (const float*)d_in[20];
    const float* ff_w2 = (const float*)d_in[21];
    const float* ff_b2 = (const float*)d_in[22];
    const float* ln1_g = (const float*)d_in[23];
    const float* ln1_b = (const float*)d_in[24];
    const float* ln2_g = (const float*)d_in[25];
    const float* ln2_b = (const float*)d_in[26];
    const float* ln3_g = (const float*)d_in[27];
    const float* ln3_b = (const float*)d_in[28];

    float* out_x    = (float*)d_out;
    float* out_attn = out_x + (size_t)cB*cSQ*cD;

    float *bufQ, *bufK, *bufV, *bufK2, *bufV2, *bufC, *bufO, *bufX1, *bufX2, *bufF;
    cudaGetSymbolAddress((void**)&bufQ,  g_bufQ);
    cudaGetSymbolAddress((void**)&bufK,  g_bufK);
    cudaGetSymbolAddress((void**)&bufV,  g_bufV);
    cudaGetSymbolAddress((void**)&bufK2, g_bufK2);
    cudaGetSymbolAddress((void**)&bufV2, g_bufV2);
    cudaGetSymbolAddress((void**)&bufC,  g_bufC);
    cudaGetSymbolAddress((void**)&bufO,  g_bufO);
    cudaGetSymbolAddress((void**)&bufX1, g_bufX1);
    cudaGetSymbolAddress((void**)&bufX2, g_bufX2);
    cudaGetSymbolAddress((void**)&bufF,  g_bufF);

    if (g_s2 == nullptr) {
        cudaStreamCreateWithFlags(&g_s2, cudaStreamNonBlocking);
        cudaEventCreateWithFlags(&g_evFork, cudaEventDisableTiming);
        cudaEventCreateWithFlags(&g_evJoin, cudaEventDisableTiming);
    }

    cudaFuncSetAttribute(attn_self_fused,
                         cudaFuncAttributeMaxDynamicSharedMemorySize, SMEM_SELF);
    cudaFuncSetAttribute(attn_cross_fused,
                         cudaFuncAttributeMaxDynamicSharedMemorySize, SMEM_CROSS);

    const float scale = 0.125f;   // 1/sqrt(64)
    const dim3 blk(256);
    const int M1 = cB * cSQ;      // 4096
    const int M2 = cB * cSK;      // 8192

    // ---- fork: cross K/V projection (depends only on enc_o) on side stream
    cudaEventRecord(g_evFork, 0);
    cudaStreamWaitEvent(g_s2, g_evFork, 0);
    gemm_fp16<false><<<dim3(cD/128, M2/128, 2), blk, 0, g_s2>>>(
        enc_o, mkset(a2_wk, a2_bk, bufK2, a2_wv, a2_bv, bufV2), M2, cD, cD);
    cudaEventRecord(g_evJoin, g_s2);

    // ---- main stream: self-attention block ----
    gemm_fp16<false><<<dim3(cD/128, M1/128, 3), blk>>>(
        x, mkset(a1_wq, a1_bq, bufQ, a1_wk, a1_bk, bufK, a1_wv, a1_bv, bufV),
        M1, cD, cD);
    attn_self_fused<<<dim3(cSQ/64, cB*cH), blk, SMEM_SELF>>>(
        bufQ, bufK, bufV, bufC, scale);
    gemm_fp16<false><<<dim3(cD/128, M1/128, 1), blk>>>(
        bufC, mkset(a1_wo, a1_bo, bufO), M1, cD, cD);
    ln_residual_kernel<<<M1, blk>>>(x, bufO, ln1_g, ln1_b, bufX1);

    // ---- cross-attention block ----
    gemm_fp16<false><<<dim3(cD/128, M1/128, 1), blk>>>(
        bufX1, mkset(a2_wq, a2_bq, bufQ), M1, cD, cD);
    cudaStreamWaitEvent(0, g_evJoin, 0);    // join side stream
    attn_cross_fused<<<dim3(cSQ/32, cB*cH), blk, SMEM_CROSS>>>(
        bufQ, bufK2, bufV2, enc_mask, out_attn, bufC, scale);
    gemm_fp16<false><<<dim3(cD/128, M1/128, 1), blk>>>(
        bufC, mkset(a2_wo, a2_bo, bufO), M1, cD, cD);
    ln_residual_kernel<<<M1, blk>>>(bufX1, bufO, ln2_g, ln2_b, bufX2);

    // ---- feed-forward ----
    gemm_fp16<true ><<<dim3(cF/128, M1/128, 1), blk>>>(
        bufX2, mkset(ff_w1, ff_b1, bufF), M1, cF, cD);
    gemm_fp16<false><<<dim3(cD/128, M1/128, 1), blk>>>(
        bufF, mkset(ff_w2, ff_b2, bufO), M1, cD, cF);
    ln_residual_kernel<<<M1, blk>>>(bufX2, bufO, ln3_g, ln3_b, out_x);
}